// round 5
// baseline (speedup 1.0000x reference)
#include <cuda_runtime.h>
#include <cuda_bf16.h>
#include <cstddef>

// Problem shapes (fixed by setup_inputs): F=2, B=64, S=512, D=768
#define Fdim  2
#define Bdim  64
#define FB    (Fdim * Bdim)      // 128
#define Sdim  512
#define Ddim  768
#define D4    (Ddim / 4)         // 192 float4 per row
#define SPLIT 8                  // S-splits per (f,b)
#define RPB   (Sdim / SPLIT)     // 64 rows per block
#define NBLK  (FB * SPLIT)       // 1024 blocks

#define EPSV  1e-9f

// Deterministic scratch (no device-side allocation allowed)
__device__ float g_partial[NBLK];
__device__ int   g_count = 0;      // last-block-done counter (self-resetting)

// ---------------------------------------------------------------------------
// Fused kernel:
//  phase 1 (all blocks): partial of T_fb = sum_s mask[s] * dot(tok[s,:], sent)
//  phase 2 (last block): T_fb = fixed-order sum of partials;
//                        out = (1/F) * sum_fb T/(T+eps)
// 192 threads == D4 lanes; each thread owns one float4 column slice.
// Masked-out rows are skipped entirely (saves ~50% of HBM traffic).
// ---------------------------------------------------------------------------
__global__ __launch_bounds__(192, 8)
void noun_fused_kernel(const float4* __restrict__ tok,
                       const float4* __restrict__ sent,
                       const int*    __restrict__ mask,
                       float*        __restrict__ out)
{
    const int fb  = blockIdx.x >> 3;        // / SPLIT
    const int sp  = blockIdx.x & (SPLIT - 1);
    const int tid = threadIdx.x;            // 0..191

    __shared__ float4 s_sent[D4];
    __shared__ int    s_mask[RPB];

    s_sent[tid] = sent[(size_t)fb * D4 + tid];
    if (tid < RPB)
        s_mask[tid] = mask[fb * Sdim + sp * RPB + tid];
    __syncthreads();

    // Hoist the 64 mask bits into two registers: predicate compute is then
    // pure ALU (no LDS on the load-issue critical path).
    unsigned mlo = 0u, mhi = 0u;
    #pragma unroll
    for (int i = 0; i < 32; i++) {
        mlo |= (s_mask[i]      ? 1u : 0u) << i;
        mhi |= (s_mask[i + 32] ? 1u : 0u) << i;
    }

    const float4 w = s_sent[tid];           // register-resident weight slice
    const float4* base = tok + ((size_t)fb * Sdim + (size_t)sp * RPB) * D4 + tid;

    float a0 = 0.f, a1 = 0.f, a2 = 0.f, a3 = 0.f;
    #pragma unroll 2
    for (int r = 0; r < RPB; r += 4) {
        const unsigned mw = (r < 32) ? mlo : mhi;
        const int      sh = r & 31;
        // 4 independent predicated rows -> 4 LDG.128 in flight, 4 FMA chains
        if ((mw >> (sh + 0)) & 1u) {
            float4 t = base[(size_t)(r + 0) * D4];
            a0 = fmaf(t.x, w.x, a0); a0 = fmaf(t.y, w.y, a0);
            a0 = fmaf(t.z, w.z, a0); a0 = fmaf(t.w, w.w, a0);
        }
        if ((mw >> (sh + 1)) & 1u) {
            float4 t = base[(size_t)(r + 1) * D4];
            a1 = fmaf(t.x, w.x, a1); a1 = fmaf(t.y, w.y, a1);
            a1 = fmaf(t.z, w.z, a1); a1 = fmaf(t.w, w.w, a1);
        }
        if ((mw >> (sh + 2)) & 1u) {
            float4 t = base[(size_t)(r + 2) * D4];
            a2 = fmaf(t.x, w.x, a2); a2 = fmaf(t.y, w.y, a2);
            a2 = fmaf(t.z, w.z, a2); a2 = fmaf(t.w, w.w, a2);
        }
        if ((mw >> (sh + 3)) & 1u) {
            float4 t = base[(size_t)(r + 3) * D4];
            a3 = fmaf(t.x, w.x, a3); a3 = fmaf(t.y, w.y, a3);
            a3 = fmaf(t.z, w.z, a3); a3 = fmaf(t.w, w.w, a3);
        }
    }
    float acc = (a0 + a1) + (a2 + a3);

    // Block reduction: 6 warps
    #pragma unroll
    for (int o = 16; o > 0; o >>= 1)
        acc += __shfl_xor_sync(0xffffffffu, acc, o);

    __shared__ float s_warp[6];
    __shared__ int   s_islast;
    if ((tid & 31) == 0)
        s_warp[tid >> 5] = acc;
    __syncthreads();

    if (tid == 0) {
        float s = 0.0f;
        #pragma unroll
        for (int i = 0; i < 6; i++) s += s_warp[i];
        g_partial[blockIdx.x] = s;          // deterministic (no atomics on data)
        __threadfence();                    // publish partial before counting
        int prev = atomicAdd(&g_count, 1);
        s_islast = (prev == NBLK - 1);
    }
    __syncthreads();

    if (!s_islast) return;

    // ---- Phase 2: last block computes the final scalar (L2-hot reads) ----
    __threadfence();                        // acquire: see all partials

    float c = 0.0f;
    if (tid < FB) {                         // 128 active lanes = warps 0..3
        float t = 0.0f;
        #pragma unroll
        for (int i = 0; i < SPLIT; i++)     // fixed order -> deterministic
            t += g_partial[tid * SPLIT + i];
        c = t / (t + EPSV);
    }

    #pragma unroll
    for (int o = 16; o > 0; o >>= 1)
        c += __shfl_xor_sync(0xffffffffu, c, o);

    if ((tid & 31) == 0)
        s_warp[tid >> 5] = c;
    __syncthreads();

    if (tid == 0) {
        out[0] = (s_warp[0] + s_warp[1] + s_warp[2] + s_warp[3]) / (float)Fdim;
        g_count = 0;                        // reset for next graph replay
    }
}

// ---------------------------------------------------------------------------
// Entry point. Inputs (metadata order):
//   d_in[0] token_embeddings   f32 [F,B,S,D]
//   d_in[1] sentence_embedding f32 [F,B,D]
//   d_in[2] attention_mask     i32 [F,B,S]
// d_out: 1 float scalar
// ---------------------------------------------------------------------------
extern "C" void kernel_launch(void* const* d_in, const int* in_sizes, int n_in,
                              void* d_out, int out_size)
{
    (void)in_sizes; (void)n_in; (void)out_size;
    const float4* tok  = (const float4*)d_in[0];
    const float4* sent = (const float4*)d_in[1];
    const int*    mask = (const int*)d_in[2];
    float*        out  = (float*)d_out;

    noun_fused_kernel<<<NBLK, 192>>>(tok, sent, mask, out);
}

// round 6
// speedup vs baseline: 1.1071x; 1.1071x over previous
#include <cuda_runtime.h>
#include <cuda_bf16.h>
#include <cstddef>

// Problem shapes (fixed by setup_inputs): F=2, B=64, S=512, D=768
#define Fdim  2
#define Bdim  64
#define FB    (Fdim * Bdim)      // 128
#define Sdim  512
#define Ddim  768
#define D4    (Ddim / 4)         // 192 float4 per row
#define SPLIT 8                  // S-splits per (f,b)
#define RPB   (Sdim / SPLIT)     // 64 rows per block
#define NBLK  (FB * SPLIT)       // 1024 blocks

#define EPSV  1e-9f

// Deterministic scratch (no device-side allocation allowed)
__device__ float g_partial[NBLK];
__device__ int   g_count = 0;      // last-block-done counter (self-resetting)

// ---------------------------------------------------------------------------
// Fused kernel, branch-free inner loop:
//  - compaction: ballot+popc builds the list of mask=1 rows in smem
//  - main loop: UNCONDITIONAL loads, 4 independent rows/iter (MLP_p1=4)
//  phase 2 (last block): T_fb = fixed-order sum of partials;
//                        out = (1/F) * sum_fb T/(T+eps)
// 192 threads == D4 lanes; each thread owns one float4 column slice.
// ---------------------------------------------------------------------------
__global__ __launch_bounds__(192, 8)
void noun_fused_kernel(const float4* __restrict__ tok,
                       const float4* __restrict__ sent,
                       const int*    __restrict__ mask,
                       float*        __restrict__ out)
{
    const int fb  = blockIdx.x >> 3;        // / SPLIT
    const int sp  = blockIdx.x & (SPLIT - 1);
    const int tid = threadIdx.x;            // 0..191

    __shared__ float4        s_sent[D4];
    __shared__ unsigned      s_ballot[2];
    __shared__ unsigned char s_rows[RPB];
    __shared__ int           s_cnt;

    s_sent[tid] = sent[(size_t)fb * D4 + tid];

    // --- Compaction: rows 0..63 handled by warps 0,1 (full-warp ballots) ---
    const int w = tid >> 5, l = tid & 31;
    if (tid < RPB) {
        int m = mask[fb * Sdim + sp * RPB + tid];
        unsigned bal = __ballot_sync(0xffffffffu, m != 0);
        if (l == 0) s_ballot[w] = bal;
    }
    __syncthreads();

    if (tid < RPB) {
        unsigned bal = s_ballot[w];
        if ((bal >> l) & 1u) {
            int pos = __popc(bal & ((1u << l) - 1u))
                    + (w ? __popc(s_ballot[0]) : 0);
            s_rows[pos] = (unsigned char)tid;
        }
        if (tid == 0)
            s_cnt = __popc(s_ballot[0]) + __popc(s_ballot[1]);
    }
    __syncthreads();

    const float4 w4 = s_sent[tid];          // register-resident weight slice
    const float4* base = tok + ((size_t)fb * Sdim + (size_t)sp * RPB) * D4 + tid;
    const int cnt = s_cnt;

    // --- Branch-free main loop: 4 unconditional independent loads/iter ---
    float a0 = 0.f, a1 = 0.f, a2 = 0.f, a3 = 0.f;
    int r = 0;
    for (; r + 4 <= cnt; r += 4) {
        const int i0 = s_rows[r + 0];
        const int i1 = s_rows[r + 1];
        const int i2 = s_rows[r + 2];
        const int i3 = s_rows[r + 3];
        float4 t0 = base[(size_t)i0 * D4];
        float4 t1 = base[(size_t)i1 * D4];
        float4 t2 = base[(size_t)i2 * D4];
        float4 t3 = base[(size_t)i3 * D4];
        a0 = fmaf(t0.x, w4.x, a0); a0 = fmaf(t0.y, w4.y, a0);
        a0 = fmaf(t0.z, w4.z, a0); a0 = fmaf(t0.w, w4.w, a0);
        a1 = fmaf(t1.x, w4.x, a1); a1 = fmaf(t1.y, w4.y, a1);
        a1 = fmaf(t1.z, w4.z, a1); a1 = fmaf(t1.w, w4.w, a1);
        a2 = fmaf(t2.x, w4.x, a2); a2 = fmaf(t2.y, w4.y, a2);
        a2 = fmaf(t2.z, w4.z, a2); a2 = fmaf(t2.w, w4.w, a2);
        a3 = fmaf(t3.x, w4.x, a3); a3 = fmaf(t3.y, w4.y, a3);
        a3 = fmaf(t3.z, w4.z, a3); a3 = fmaf(t3.w, w4.w, a3);
    }
    for (; r < cnt; ++r) {                  // <=3 remainder rows
        float4 t = base[(size_t)s_rows[r] * D4];
        a0 = fmaf(t.x, w4.x, a0); a0 = fmaf(t.y, w4.y, a0);
        a0 = fmaf(t.z, w4.z, a0); a0 = fmaf(t.w, w4.w, a0);
    }
    float acc = (a0 + a1) + (a2 + a3);

    // --- Block reduction: 6 warps ---
    #pragma unroll
    for (int o = 16; o > 0; o >>= 1)
        acc += __shfl_xor_sync(0xffffffffu, acc, o);

    __shared__ float s_warp[6];
    __shared__ int   s_islast;
    if (l == 0)
        s_warp[w] = acc;
    __syncthreads();

    if (tid == 0) {
        float s = 0.0f;
        #pragma unroll
        for (int i = 0; i < 6; i++) s += s_warp[i];
        g_partial[blockIdx.x] = s;          // deterministic (no atomics on data)
        __threadfence();                    // publish partial before counting
        int prev = atomicAdd(&g_count, 1);
        s_islast = (prev == NBLK - 1);
    }
    __syncthreads();

    if (!s_islast) return;

    // ---- Phase 2: last block computes the final scalar (L2-hot reads) ----
    __threadfence();                        // acquire: see all partials

    float c = 0.0f;
    if (tid < FB) {                         // 128 active lanes = warps 0..3
        float t = 0.0f;
        #pragma unroll
        for (int i = 0; i < SPLIT; i++)     // fixed order -> deterministic
            t += g_partial[tid * SPLIT + i];
        c = t / (t + EPSV);
    }

    #pragma unroll
    for (int o = 16; o > 0; o >>= 1)
        c += __shfl_xor_sync(0xffffffffu, c, o);

    if (l == 0)
        s_warp[w] = c;
    __syncthreads();

    if (tid == 0) {
        out[0] = (s_warp[0] + s_warp[1] + s_warp[2] + s_warp[3]) / (float)Fdim;
        g_count = 0;                        // reset for next graph replay
    }
}

// ---------------------------------------------------------------------------
// Entry point. Inputs (metadata order):
//   d_in[0] token_embeddings   f32 [F,B,S,D]
//   d_in[1] sentence_embedding f32 [F,B,D]
//   d_in[2] attention_mask     i32 [F,B,S]
// d_out: 1 float scalar
// ---------------------------------------------------------------------------
extern "C" void kernel_launch(void* const* d_in, const int* in_sizes, int n_in,
                              void* d_out, int out_size)
{
    (void)in_sizes; (void)n_in; (void)out_size;
    const float4* tok  = (const float4*)d_in[0];
    const float4* sent = (const float4*)d_in[1];
    const int*    mask = (const int*)d_in[2];
    float*        out  = (float*)d_out;

    noun_fused_kernel<<<NBLK, 192>>>(tok, sent, mask, out);
}